// round 1
// baseline (speedup 1.0000x reference)
#include <cuda_runtime.h>

#define NNODES 50000
#define EEDGES 800000
#define ETOT   (EEDGES + NNODES)   // 850000, with self-loops
#define FIN    128
#define HC     128                  // H*C
#define NHEAD  2
#define NCLS   16
#define NEG    0.2f

// ---------------- scratch (device globals; no allocation allowed) ----------
__device__ float    g_h[(size_t)NNODES * HC];        // 25.6 MB
__device__ float    g_asrc[NNODES * NHEAD];
__device__ float    g_adst[NNODES * NHEAD];
__device__ unsigned g_menc[NNODES * NHEAD];          // encoded segment max
__device__ float    g_den[NNODES * NHEAD];
__device__ float    g_e[(size_t)ETOT * NHEAD];       // e, then exp(e-m)
__device__ float    g_agg[(size_t)NNODES * HC];      // 25.6 MB
__device__ int      g_idx64;                         // 1 if edge_index is int64

// monotone float <-> unsigned encoding for atomicMax on floats (incl. negatives)
__device__ __forceinline__ unsigned f_enc(float f) {
    unsigned b = __float_as_uint(f);
    return (b & 0x80000000u) ? ~b : (b | 0x80000000u);
}
__device__ __forceinline__ float f_dec(unsigned u) {
    return (u & 0x80000000u) ? __uint_as_float(u ^ 0x80000000u)
                             : __uint_as_float(~u);
}

__device__ __forceinline__ void load_edge(const void* ei, int t, int& s, int& d) {
    if (t >= EEDGES) { s = d = t - EEDGES; return; }   // appended self-loop
    if (g_idx64) {
        const long long* p = (const long long*)ei;
        s = (int)p[t]; d = (int)p[EEDGES + t];
    } else {
        const int* p = (const int*)ei;
        s = p[t]; d = p[EEDGES + t];
    }
}

// ---------------- index-width detection -----------------------------------
__global__ void k_detect(const void* ei) {
    if (threadIdx.x == 0 && blockIdx.x == 0) {
        const long long* p = (const long long*)ei;
        int ok = 1;
        for (int i = 0; i < 256; i++) {
            long long v = p[i];
            if (v < 0 || v >= NNODES) { ok = 0; break; }
        }
        g_idx64 = ok;
    }
}

// ---------------- h = x @ W  (M=50000, K=128, N=128) -----------------------
// 64x64 tile per 256-thread block, BK=32, 4x4 register micro-tile.
__global__ void k_gemm(const float* __restrict__ x, const float* __restrict__ W) {
    __shared__ float xs[64][32];
    __shared__ float ws[32][64];
    int tid = threadIdx.x;
    int col0 = blockIdx.x * 64;          // 0 or 64
    int row0 = blockIdx.y * 64;
    int ty = tid >> 4, tx = tid & 15;
    float acc[4][4] = {};

    for (int kt = 0; kt < FIN; kt += 32) {
        #pragma unroll
        for (int i = 0; i < 2; i++) {                  // xs: 512 float4 loads
            int lin = tid + i * 256;
            int r = lin >> 3, kk = (lin & 7) << 2;
            int gr = row0 + r;
            float4 v = make_float4(0.f, 0.f, 0.f, 0.f);
            if (gr < NNODES) v = *(const float4*)&x[(size_t)gr * FIN + kt + kk];
            xs[r][kk] = v.x; xs[r][kk + 1] = v.y; xs[r][kk + 2] = v.z; xs[r][kk + 3] = v.w;
        }
        #pragma unroll
        for (int i = 0; i < 2; i++) {                  // ws: 512 float4 loads
            int lin = tid + i * 256;
            int k = lin >> 4, cc = (lin & 15) << 2;
            float4 v = *(const float4*)&W[(size_t)(kt + k) * HC + col0 + cc];
            ws[k][cc] = v.x; ws[k][cc + 1] = v.y; ws[k][cc + 2] = v.z; ws[k][cc + 3] = v.w;
        }
        __syncthreads();
        #pragma unroll
        for (int k = 0; k < 32; k++) {
            float a[4], b[4];
            #pragma unroll
            for (int i = 0; i < 4; i++) a[i] = xs[ty * 4 + i][k];
            #pragma unroll
            for (int j = 0; j < 4; j++) b[j] = ws[k][tx * 4 + j];
            #pragma unroll
            for (int i = 0; i < 4; i++)
                #pragma unroll
                for (int j = 0; j < 4; j++)
                    acc[i][j] += a[i] * b[j];
        }
        __syncthreads();
    }
    #pragma unroll
    for (int i = 0; i < 4; i++) {
        int gr = row0 + ty * 4 + i;
        if (gr < NNODES) {
            float4 v = make_float4(acc[i][0], acc[i][1], acc[i][2], acc[i][3]);
            *(float4*)&g_h[(size_t)gr * HC + col0 + tx * 4] = v;
        }
    }
}

// ---------------- per-node attention coefficients --------------------------
__global__ void k_att(const float* __restrict__ att_src, const float* __restrict__ att_dst) {
    int node = (blockIdx.x * blockDim.x + threadIdx.x) >> 5;
    int lane = threadIdx.x & 31;
    if (node >= NNODES) return;
    const float* hr = &g_h[(size_t)node * HC];
    float v0 = hr[lane], v1 = hr[32 + lane], v2 = hr[64 + lane], v3 = hr[96 + lane];
    float s0 = v0 * att_src[lane] + v1 * att_src[32 + lane];
    float s1 = v2 * att_src[64 + lane] + v3 * att_src[96 + lane];
    float d0 = v0 * att_dst[lane] + v1 * att_dst[32 + lane];
    float d1 = v2 * att_dst[64 + lane] + v3 * att_dst[96 + lane];
    #pragma unroll
    for (int o = 16; o; o >>= 1) {
        s0 += __shfl_xor_sync(0xffffffffu, s0, o);
        s1 += __shfl_xor_sync(0xffffffffu, s1, o);
        d0 += __shfl_xor_sync(0xffffffffu, d0, o);
        d1 += __shfl_xor_sync(0xffffffffu, d1, o);
    }
    if (lane == 0) {
        g_asrc[node * 2] = s0; g_asrc[node * 2 + 1] = s1;
        g_adst[node * 2] = d0; g_adst[node * 2 + 1] = d1;
    }
}

// ---------------- zero scratch ---------------------------------------------
__global__ void k_zero() {
    int stride = gridDim.x * blockDim.x;
    for (size_t i = blockIdx.x * blockDim.x + threadIdx.x; i < (size_t)NNODES * HC; i += stride) {
        g_agg[i] = 0.f;
        if (i < NNODES * NHEAD) { g_den[i] = 0.f; g_menc[i] = 0u; }
    }
}

// ---------------- edge pass 1: e + segment max -----------------------------
__global__ void k_edge1(const void* __restrict__ ei) {
    int t = blockIdx.x * blockDim.x + threadIdx.x;
    if (t >= ETOT) return;
    int s, d; load_edge(ei, t, s, d);
    float e0 = g_asrc[s * 2]     + g_adst[d * 2];
    float e1 = g_asrc[s * 2 + 1] + g_adst[d * 2 + 1];
    e0 = e0 > 0.f ? e0 : NEG * e0;
    e1 = e1 > 0.f ? e1 : NEG * e1;
    g_e[(size_t)t * 2]     = e0;
    g_e[(size_t)t * 2 + 1] = e1;
    atomicMax(&g_menc[d * 2],     f_enc(e0));
    atomicMax(&g_menc[d * 2 + 1], f_enc(e1));
}

// ---------------- edge pass 2: exp + segment sum ---------------------------
__global__ void k_edge2(const void* __restrict__ ei) {
    int t = blockIdx.x * blockDim.x + threadIdx.x;
    if (t >= ETOT) return;
    int s, d; load_edge(ei, t, s, d);
    (void)s;
    float m0 = f_dec(g_menc[d * 2]);
    float m1 = f_dec(g_menc[d * 2 + 1]);
    float ex0 = __expf(g_e[(size_t)t * 2]     - m0);
    float ex1 = __expf(g_e[(size_t)t * 2 + 1] - m1);
    g_e[(size_t)t * 2]     = ex0;
    g_e[(size_t)t * 2 + 1] = ex1;
    atomicAdd(&g_den[d * 2],     ex0);
    atomicAdd(&g_den[d * 2 + 1], ex1);
}

// ---------------- edge pass 3: weighted scatter (warp per edge) ------------
__global__ void k_scatter(const void* __restrict__ ei) {
    int t = (blockIdx.x * blockDim.x + threadIdx.x) >> 5;
    int lane = threadIdx.x & 31;
    if (t >= ETOT) return;
    int s, d; load_edge(ei, t, s, d);
    float a0 = g_e[(size_t)t * 2]     / (g_den[d * 2]     + 1e-16f);
    float a1 = g_e[(size_t)t * 2 + 1] / (g_den[d * 2 + 1] + 1e-16f);
    float al = (lane < 16) ? a0 : a1;           // channels 0-63 head0, 64-127 head1
    float4 hv = *(const float4*)&g_h[(size_t)s * HC + lane * 4];
    float* dp = &g_agg[(size_t)d * HC + lane * 4];
    atomicAdd(dp,     hv.x * al);
    atomicAdd(dp + 1, hv.y * al);
    atomicAdd(dp + 2, hv.z * al);
    atomicAdd(dp + 3, hv.w * al);
}

// ---------------- epilogue: relu -> fc -> log_softmax ----------------------
__global__ void k_final(const float* __restrict__ bias, const float* __restrict__ Wfc,
                        const float* __restrict__ bfc, float* __restrict__ out) {
    __shared__ float wt[NCLS * HC];   // transposed: wt[c*128+k], 8 KB
    int tid = threadIdx.x;
    for (int i = tid; i < NCLS * HC; i += blockDim.x) {
        int c = i >> 7, k = i & 127;
        wt[i] = Wfc[k * NCLS + c];
    }
    __syncthreads();
    int node = blockIdx.x * (blockDim.x >> 5) + (tid >> 5);
    int lane = tid & 31;
    if (node >= NNODES) return;

    const float* ar = &g_agg[(size_t)node * HC];
    float4 av = *(const float4*)&ar[lane * 4];
    float4 bv = *(const float4*)&bias[lane * 4];
    float v[4] = { fmaxf(av.x + bv.x, 0.f), fmaxf(av.y + bv.y, 0.f),
                   fmaxf(av.z + bv.z, 0.f), fmaxf(av.w + bv.w, 0.f) };

    float acc[NCLS];
    #pragma unroll
    for (int c = 0; c < NCLS; c++) acc[c] = 0.f;
    #pragma unroll
    for (int i = 0; i < 4; i++) {
        int k = lane * 4 + i;
        #pragma unroll
        for (int c = 0; c < NCLS; c++) acc[c] += v[i] * wt[c * HC + k];
    }
    #pragma unroll
    for (int c = 0; c < NCLS; c++)
        #pragma unroll
        for (int o = 16; o; o >>= 1) acc[c] += __shfl_xor_sync(0xffffffffu, acc[c], o);

    if (lane == 0) {
        float mx = -3.402823466e38f;
        #pragma unroll
        for (int c = 0; c < NCLS; c++) { acc[c] += bfc[c]; mx = fmaxf(mx, acc[c]); }
        float se = 0.f;
        #pragma unroll
        for (int c = 0; c < NCLS; c++) se += __expf(acc[c] - mx);
        float lse = mx + logf(se);
        #pragma unroll
        for (int c = 0; c < NCLS; c++) out[(size_t)node * NCLS + c] = acc[c] - lse;
    }
}

// ---------------- launch ----------------------------------------------------
extern "C" void kernel_launch(void* const* d_in, const int* in_sizes, int n_in,
                              void* d_out, int out_size) {
    const float* x        = (const float*)d_in[0];
    const void*  ei       = d_in[1];
    const float* W        = (const float*)d_in[2];
    const float* att_src  = (const float*)d_in[3];
    const float* att_dst  = (const float*)d_in[4];
    const float* bias     = (const float*)d_in[5];
    const float* Wfc      = (const float*)d_in[6];
    const float* bfc      = (const float*)d_in[7];
    float* out = (float*)d_out;

    k_detect<<<1, 32>>>(ei);

    dim3 gg(2, (NNODES + 63) / 64);
    k_gemm<<<gg, 256>>>(x, W);
    k_att<<<(NNODES * 32 + 255) / 256, 256>>>(att_src, att_dst);
    k_zero<<<2048, 256>>>();
    k_edge1<<<(ETOT + 255) / 256, 256>>>(ei);
    k_edge2<<<(ETOT + 255) / 256, 256>>>(ei);
    {
        long long threads = (long long)ETOT * 32;
        int blocks = (int)((threads + 255) / 256);
        k_scatter<<<blocks, 256>>>(ei);
    }
    k_final<<<(NNODES + 7) / 8, 256>>>(bias, Wfc, bfc, out);
}

// round 2
// speedup vs baseline: 1.7669x; 1.7669x over previous
#include <cuda_runtime.h>
#include <math_constants.h>

#define NNODES 50000
#define EEDGES 800000
#define ETOT   (EEDGES + NNODES)   // 850000 with self-loops
#define FIN    128
#define HC     128
#define NHEAD  2
#define NCLS   16
#define NEG    0.2f
#define SCAN_T 1024

// ---------------- scratch ----------------
__device__ float g_h[(size_t)NNODES * HC];       // 25.6 MB
__device__ float g_asrc[NNODES * NHEAD];         // [node*2+h]
__device__ float g_adst[NNODES * NHEAD];
__device__ int   g_cnt[NNODES];                  // degree counters
__device__ int   g_cur[NNODES];                  // fill cursors
__device__ int   g_off[NNODES + 1];              // CSR offsets
__device__ int   g_csrc[ETOT];                   // CSR src lists (dst-major)
__device__ int   g_idx64;

__device__ __forceinline__ void load_edge(const void* ei, int t, int& s, int& d) {
    if (t >= EEDGES) { s = d = t - EEDGES; return; }
    if (g_idx64) {
        const long long* p = (const long long*)ei;
        s = (int)p[t]; d = (int)p[EEDGES + t];
    } else {
        const int* p = (const int*)ei;
        s = p[t]; d = p[EEDGES + t];
    }
}

__global__ void k_detect(const void* ei) {
    if (threadIdx.x == 0 && blockIdx.x == 0) {
        const long long* p = (const long long*)ei;
        int ok = 1;
        for (int i = 0; i < 256; i++) {
            long long v = p[i];
            if (v < 0 || v >= NNODES) { ok = 0; break; }
        }
        g_idx64 = ok;
    }
}

__global__ void k_zero() {
    int i = blockIdx.x * blockDim.x + threadIdx.x;
    if (i < NNODES) { g_cnt[i] = 0; g_cur[i] = 0; }
}

// ---------------- h = x @ W -----------------------------------------------
__global__ void k_gemm(const float* __restrict__ x, const float* __restrict__ W) {
    __shared__ float xs[64][32];
    __shared__ float ws[32][64];
    int tid = threadIdx.x;
    int col0 = blockIdx.x * 64;
    int row0 = blockIdx.y * 64;
    int ty = tid >> 4, tx = tid & 15;
    float acc[4][4] = {};

    for (int kt = 0; kt < FIN; kt += 32) {
        #pragma unroll
        for (int i = 0; i < 2; i++) {
            int lin = tid + i * 256;
            int r = lin >> 3, kk = (lin & 7) << 2;
            int gr = row0 + r;
            float4 v = make_float4(0.f, 0.f, 0.f, 0.f);
            if (gr < NNODES) v = *(const float4*)&x[(size_t)gr * FIN + kt + kk];
            xs[r][kk] = v.x; xs[r][kk + 1] = v.y; xs[r][kk + 2] = v.z; xs[r][kk + 3] = v.w;
        }
        #pragma unroll
        for (int i = 0; i < 2; i++) {
            int lin = tid + i * 256;
            int k = lin >> 4, cc = (lin & 15) << 2;
            float4 v = *(const float4*)&W[(size_t)(kt + k) * HC + col0 + cc];
            ws[k][cc] = v.x; ws[k][cc + 1] = v.y; ws[k][cc + 2] = v.z; ws[k][cc + 3] = v.w;
        }
        __syncthreads();
        #pragma unroll
        for (int k = 0; k < 32; k++) {
            float a[4], b[4];
            #pragma unroll
            for (int i = 0; i < 4; i++) a[i] = xs[ty * 4 + i][k];
            #pragma unroll
            for (int j = 0; j < 4; j++) b[j] = ws[k][tx * 4 + j];
            #pragma unroll
            for (int i = 0; i < 4; i++)
                #pragma unroll
                for (int j = 0; j < 4; j++)
                    acc[i][j] += a[i] * b[j];
        }
        __syncthreads();
    }
    #pragma unroll
    for (int i = 0; i < 4; i++) {
        int gr = row0 + ty * 4 + i;
        if (gr < NNODES)
            *(float4*)&g_h[(size_t)gr * HC + col0 + tx * 4] =
                make_float4(acc[i][0], acc[i][1], acc[i][2], acc[i][3]);
    }
}

// ---------------- per-node attention coefficients --------------------------
__global__ void k_att(const float* __restrict__ att_src, const float* __restrict__ att_dst) {
    int node = (blockIdx.x * blockDim.x + threadIdx.x) >> 5;
    int lane = threadIdx.x & 31;
    if (node >= NNODES) return;
    const float* hr = &g_h[(size_t)node * HC];
    float v0 = hr[lane], v1 = hr[32 + lane], v2 = hr[64 + lane], v3 = hr[96 + lane];
    float s0 = v0 * att_src[lane] + v1 * att_src[32 + lane];
    float s1 = v2 * att_src[64 + lane] + v3 * att_src[96 + lane];
    float d0 = v0 * att_dst[lane] + v1 * att_dst[32 + lane];
    float d1 = v2 * att_dst[64 + lane] + v3 * att_dst[96 + lane];
    #pragma unroll
    for (int o = 16; o; o >>= 1) {
        s0 += __shfl_xor_sync(0xffffffffu, s0, o);
        s1 += __shfl_xor_sync(0xffffffffu, s1, o);
        d0 += __shfl_xor_sync(0xffffffffu, d0, o);
        d1 += __shfl_xor_sync(0xffffffffu, d1, o);
    }
    if (lane == 0) {
        g_asrc[node * 2] = s0; g_asrc[node * 2 + 1] = s1;
        g_adst[node * 2] = d0; g_adst[node * 2 + 1] = d1;
    }
}

// ---------------- CSR build -------------------------------------------------
__global__ void k_count(const void* __restrict__ ei) {
    int t = blockIdx.x * blockDim.x + threadIdx.x;
    if (t >= ETOT) return;
    int s, d; load_edge(ei, t, s, d); (void)s;
    atomicAdd(&g_cnt[d], 1);
}

__global__ void k_scan() {
    __shared__ int sd[SCAN_T];
    int tid = threadIdx.x;
    const int per = (NNODES + SCAN_T - 1) / SCAN_T;   // 49
    int start = tid * per;
    int end = start + per; if (end > NNODES) end = NNODES;
    int sum = 0;
    for (int i = start; i < end; i++) sum += g_cnt[i];
    sd[tid] = sum;
    __syncthreads();
    for (int o = 1; o < SCAN_T; o <<= 1) {
        int v = (tid >= o) ? sd[tid - o] : 0;
        __syncthreads();
        sd[tid] += v;
        __syncthreads();
    }
    int run = (tid > 0) ? sd[tid - 1] : 0;
    for (int i = start; i < end; i++) { g_off[i] = run; run += g_cnt[i]; }
    if (tid == SCAN_T - 1) g_off[NNODES] = run;
}

__global__ void k_fill(const void* __restrict__ ei) {
    int t = blockIdx.x * blockDim.x + threadIdx.x;
    if (t >= ETOT) return;
    int s, d; load_edge(ei, t, s, d);
    int pos = g_off[d] + atomicAdd(&g_cur[d], 1);
    g_csrc[pos] = s;
}

// ---------------- fused: softmax + aggregate + bias/relu/fc/log_softmax -----
__global__ void k_agg(const float* __restrict__ bias, const float* __restrict__ Wfc,
                      const float* __restrict__ bfc, float* __restrict__ out) {
    __shared__ float wt[NCLS * HC];        // transposed fc weights
    int tid = threadIdx.x;
    for (int i = tid; i < NCLS * HC; i += blockDim.x) {
        int c = i >> 7, k = i & 127;
        wt[i] = Wfc[k * NCLS + c];
    }
    __syncthreads();

    int node = blockIdx.x * (blockDim.x >> 5) + (tid >> 5);
    int lane = tid & 31;
    if (node >= NNODES) return;

    int off = g_off[node];
    int deg = g_off[node + 1] - off;
    float ad0 = g_adst[node * 2], ad1 = g_adst[node * 2 + 1];

    // pass 1: segment max per head
    float m0 = -CUDART_INF_F, m1 = -CUDART_INF_F;
    for (int base = 0; base < deg; base += 32) {
        int i = base + lane;
        if (i < deg) {
            int s = g_csrc[off + i];
            float2 as = *(const float2*)&g_asrc[s * 2];
            float e0 = as.x + ad0, e1 = as.y + ad1;
            e0 = e0 > 0.f ? e0 : NEG * e0;
            e1 = e1 > 0.f ? e1 : NEG * e1;
            m0 = fmaxf(m0, e0); m1 = fmaxf(m1, e1);
        }
    }
    #pragma unroll
    for (int o = 16; o; o >>= 1) {
        m0 = fmaxf(m0, __shfl_xor_sync(0xffffffffu, m0, o));
        m1 = fmaxf(m1, __shfl_xor_sync(0xffffffffu, m1, o));
    }

    // pass 2: accumulate exp-weighted h[src] (lane owns channels lane*4..+3)
    int head = (lane >> 4);                 // ch 0-63 head0, 64-127 head1
    float mh = head ? m1 : m0;
    float acc0 = 0.f, acc1 = 0.f, acc2 = 0.f, acc3 = 0.f, den = 0.f;

    for (int base = 0; base < deg; base += 32) {
        int myi = base + lane;
        int sA = (myi < deg) ? g_csrc[off + myi] : 0;
        int nthis = deg - base; if (nthis > 32) nthis = 32;
        for (int j = 0; j < nthis; j++) {
            int s = __shfl_sync(0xffffffffu, sA, j);
            float2 as = *(const float2*)&g_asrc[s * 2];
            float e = (head ? as.y + ad1 : as.x + ad0);
            e = e > 0.f ? e : NEG * e;
            float w = __expf(e - mh);
            den += w;
            float4 hv = *(const float4*)&g_h[(size_t)s * HC + lane * 4];
            acc0 += hv.x * w; acc1 += hv.y * w; acc2 += hv.z * w; acc3 += hv.w * w;
        }
    }
    float inv = 1.f / (den + 1e-16f);
    float4 bv = *(const float4*)&bias[lane * 4];
    float v0 = fmaxf(acc0 * inv + bv.x, 0.f);
    float v1 = fmaxf(acc1 * inv + bv.y, 0.f);
    float v2 = fmaxf(acc2 * inv + bv.z, 0.f);
    float v3 = fmaxf(acc3 * inv + bv.w, 0.f);

    // fc: 128 -> 16
    float fa[NCLS];
    int k0 = lane * 4;
    #pragma unroll
    for (int c = 0; c < NCLS; c++) {
        const float* wr = &wt[c * HC + k0];
        fa[c] = v0 * wr[0] + v1 * wr[1] + v2 * wr[2] + v3 * wr[3];
    }
    #pragma unroll
    for (int c = 0; c < NCLS; c++)
        #pragma unroll
        for (int o = 16; o; o >>= 1) fa[c] += __shfl_xor_sync(0xffffffffu, fa[c], o);

    if (lane == 0) {
        float mx = -CUDART_INF_F;
        #pragma unroll
        for (int c = 0; c < NCLS; c++) { fa[c] += bfc[c]; mx = fmaxf(mx, fa[c]); }
        float se = 0.f;
        #pragma unroll
        for (int c = 0; c < NCLS; c++) se += __expf(fa[c] - mx);
        float lse = mx + logf(se);
        #pragma unroll
        for (int c = 0; c < NCLS; c++) out[(size_t)node * NCLS + c] = fa[c] - lse;
    }
}

// ---------------- launch ----------------------------------------------------
extern "C" void kernel_launch(void* const* d_in, const int* in_sizes, int n_in,
                              void* d_out, int out_size) {
    const float* x       = (const float*)d_in[0];
    const void*  ei      = d_in[1];
    const float* W       = (const float*)d_in[2];
    const float* att_src = (const float*)d_in[3];
    const float* att_dst = (const float*)d_in[4];
    const float* bias    = (const float*)d_in[5];
    const float* Wfc     = (const float*)d_in[6];
    const float* bfc     = (const float*)d_in[7];
    float* out = (float*)d_out;

    k_detect<<<1, 32>>>(ei);
    k_zero<<<(NNODES + 255) / 256, 256>>>();

    dim3 gg(2, (NNODES + 63) / 64);
    k_gemm<<<gg, 256>>>(x, W);
    k_att<<<(NNODES * 32 + 255) / 256, 256>>>(att_src, att_dst);

    k_count<<<(ETOT + 255) / 256, 256>>>(ei);
    k_scan<<<1, SCAN_T>>>();
    k_fill<<<(ETOT + 255) / 256, 256>>>(ei);

    k_agg<<<(NNODES + 7) / 8, 256>>>(bias, Wfc, bfc, out);
}

// round 3
// speedup vs baseline: 1.9540x; 1.1059x over previous
#include <cuda_runtime.h>
#include <math_constants.h>

#define NNODES 50000
#define EEDGES 800000
#define ETOT   (EEDGES + NNODES)
#define FIN    128
#define HC     128
#define NHEAD  2
#define NCLS   16
#define NEG    0.2f
#define SCAN_T 1024
#define WPB    8

// ---------------- scratch ----------------
__device__ float g_h[(size_t)NNODES * HC];
__device__ float g_asrc[NNODES * NHEAD];
__device__ float g_adst[NNODES * NHEAD];
__device__ int   g_cnt[NNODES];
__device__ int   g_cur[NNODES];
__device__ int   g_off[NNODES + 1];
__device__ int   g_csrc[ETOT];
__device__ int   g_idx64;

__device__ __forceinline__ void load_edge(const void* ei, int t, int& s, int& d) {
    if (t >= EEDGES) { s = d = t - EEDGES; return; }
    if (g_idx64) {
        const long long* p = (const long long*)ei;
        s = (int)p[t]; d = (int)p[EEDGES + t];
    } else {
        const int* p = (const int*)ei;
        s = p[t]; d = p[EEDGES + t];
    }
}

// ---------------- init: zero counters + warp-parallel dtype detect ---------
__global__ void k_init(const void* ei) {
    int i = blockIdx.x * blockDim.x + threadIdx.x;
    if (i < NNODES) { g_cnt[i] = 0; g_cur[i] = 0; }
    if (blockIdx.x == 0 && threadIdx.x < 32) {
        const long long* p = (const long long*)ei;
        int ok = 1;
        #pragma unroll
        for (int r = 0; r < 8; r++) {
            long long v = p[threadIdx.x + r * 32];
            if (v < 0 || v >= NNODES) ok = 0;
        }
        ok = __all_sync(0xffffffffu, ok);
        if (threadIdx.x == 0) g_idx64 = ok;
    }
}

// ---------------- h = x @ W with fused attention-coefficient epilogue ------
__global__ void k_gemm(const float* __restrict__ x, const float* __restrict__ W,
                       const float* __restrict__ att_src, const float* __restrict__ att_dst) {
    __shared__ float xs[64][32];
    __shared__ float ws[32][64];
    int tid = threadIdx.x;
    int head = blockIdx.x;               // col0 = head*64: block owns one full head
    int col0 = head * 64;
    int row0 = blockIdx.y * 64;
    int ty = tid >> 4, tx = tid & 15;
    float acc[4][4] = {};

    for (int kt = 0; kt < FIN; kt += 32) {
        #pragma unroll
        for (int i = 0; i < 2; i++) {
            int lin = tid + i * 256;
            int r = lin >> 3, kk = (lin & 7) << 2;
            int gr = row0 + r;
            float4 v = make_float4(0.f, 0.f, 0.f, 0.f);
            if (gr < NNODES) v = *(const float4*)&x[(size_t)gr * FIN + kt + kk];
            xs[r][kk] = v.x; xs[r][kk + 1] = v.y; xs[r][kk + 2] = v.z; xs[r][kk + 3] = v.w;
        }
        #pragma unroll
        for (int i = 0; i < 2; i++) {
            int lin = tid + i * 256;
            int k = lin >> 4, cc = (lin & 15) << 2;
            float4 v = *(const float4*)&W[(size_t)(kt + k) * HC + col0 + cc];
            ws[k][cc] = v.x; ws[k][cc + 1] = v.y; ws[k][cc + 2] = v.z; ws[k][cc + 3] = v.w;
        }
        __syncthreads();
        #pragma unroll
        for (int k = 0; k < 32; k++) {
            float a[4], b[4];
            #pragma unroll
            for (int i = 0; i < 4; i++) a[i] = xs[ty * 4 + i][k];
            #pragma unroll
            for (int j = 0; j < 4; j++) b[j] = ws[k][tx * 4 + j];
            #pragma unroll
            for (int i = 0; i < 4; i++)
                #pragma unroll
                for (int j = 0; j < 4; j++)
                    acc[i][j] += a[i] * b[j];
        }
        __syncthreads();
    }

    // att vectors for my 4 columns (att_src flattened (H,C) == global col index)
    float asv[4], adv[4];
    #pragma unroll
    for (int j = 0; j < 4; j++) {
        asv[j] = att_src[col0 + tx * 4 + j];
        adv[j] = att_dst[col0 + tx * 4 + j];
    }

    float ps[4], pd[4];
    #pragma unroll
    for (int i = 0; i < 4; i++) {
        int gr = row0 + ty * 4 + i;
        ps[i] = acc[i][0] * asv[0] + acc[i][1] * asv[1] + acc[i][2] * asv[2] + acc[i][3] * asv[3];
        pd[i] = acc[i][0] * adv[0] + acc[i][1] * adv[1] + acc[i][2] * adv[2] + acc[i][3] * adv[3];
        if (gr < NNODES)
            *(float4*)&g_h[(size_t)gr * HC + col0 + tx * 4] =
                make_float4(acc[i][0], acc[i][1], acc[i][2], acc[i][3]);
    }
    // reduce across the 16 tx-lanes (contiguous 16-lane halves of the warp)
    #pragma unroll
    for (int o = 8; o; o >>= 1) {
        #pragma unroll
        for (int i = 0; i < 4; i++) {
            ps[i] += __shfl_xor_sync(0xffffffffu, ps[i], o);
            pd[i] += __shfl_xor_sync(0xffffffffu, pd[i], o);
        }
    }
    if (tx == 0) {
        #pragma unroll
        for (int i = 0; i < 4; i++) {
            int gr = row0 + ty * 4 + i;
            if (gr < NNODES) {
                g_asrc[gr * 2 + head] = ps[i];
                g_adst[gr * 2 + head] = pd[i];
            }
        }
    }
}

// ---------------- CSR build -------------------------------------------------
__global__ void k_count(const void* __restrict__ ei) {
    int t = blockIdx.x * blockDim.x + threadIdx.x;
    if (t >= ETOT) return;
    int s, d; load_edge(ei, t, s, d); (void)s;
    atomicAdd(&g_cnt[d], 1);
}

__global__ void k_scan() {
    __shared__ int sd[SCAN_T];
    int tid = threadIdx.x;
    const int per = (NNODES + SCAN_T - 1) / SCAN_T;
    int start = tid * per;
    int end = start + per; if (end > NNODES) end = NNODES;
    int sum = 0;
    for (int i = start; i < end; i++) sum += g_cnt[i];
    sd[tid] = sum;
    __syncthreads();
    for (int o = 1; o < SCAN_T; o <<= 1) {
        int v = (tid >= o) ? sd[tid - o] : 0;
        __syncthreads();
        sd[tid] += v;
        __syncthreads();
    }
    int run = (tid > 0) ? sd[tid - 1] : 0;
    for (int i = start; i < end; i++) { g_off[i] = run; run += g_cnt[i]; }
    if (tid == SCAN_T - 1) g_off[NNODES] = run;
}

__global__ void k_fill(const void* __restrict__ ei) {
    int t = blockIdx.x * blockDim.x + threadIdx.x;
    if (t >= ETOT) return;
    int s, d; load_edge(ei, t, s, d);
    int pos = g_off[d] + atomicAdd(&g_cur[d], 1);
    g_csrc[pos] = s;
}

// ---------------- fused softmax-aggregate + bias/relu/fc/log_softmax --------
__global__ void k_agg(const float* __restrict__ bias, const float* __restrict__ Wfc,
                      const float* __restrict__ bfc, float* __restrict__ out) {
    __shared__ float wt[NCLS * HC];
    __shared__ int   sh_s[WPB][32];
    __shared__ float sh_w0[WPB][32];
    __shared__ float sh_w1[WPB][32];
    int tid = threadIdx.x;
    for (int i = tid; i < NCLS * HC; i += blockDim.x) {
        int c = i >> 7, k = i & 127;
        wt[i] = Wfc[k * NCLS + c];
    }
    __syncthreads();

    int wid = tid >> 5, lane = tid & 31;
    int node = blockIdx.x * WPB + wid;
    if (node >= NNODES) return;

    int off = g_off[node];
    int deg = g_off[node + 1] - off;
    float ad0 = g_adst[node * 2], ad1 = g_adst[node * 2 + 1];
    int head = lane >> 4;                     // ch 0-63 -> head0, 64-127 -> head1

    float acc0 = 0.f, acc1 = 0.f, acc2 = 0.f, acc3 = 0.f, den = 0.f;

    for (int base = 0; base < deg; base += 32) {
        int i = base + lane;
        int s = 0; float w0 = 0.f, w1 = 0.f;
        if (i < deg) {
            s = g_csrc[off + i];
            float2 as = *(const float2*)&g_asrc[s * 2];
            float e0 = as.x + ad0, e1 = as.y + ad1;
            e0 = e0 > 0.f ? e0 : NEG * e0;
            e1 = e1 > 0.f ? e1 : NEG * e1;
            w0 = __expf(e0); w1 = __expf(e1);   // no max-subtraction: |e| small
        }
        sh_s[wid][lane] = s; sh_w0[wid][lane] = w0; sh_w1[wid][lane] = w1;
        __syncwarp();

        int nthis = deg - base; if (nthis > 32) nthis = 32;
        int nproc = (nthis + 3) & ~3;          // pad to 4; padded lanes have w=0,s=0
        const float* whp = head ? sh_w1[wid] : sh_w0[wid];
        for (int j = 0; j < nproc; j += 4) {
            int s0 = sh_s[wid][j], s1 = sh_s[wid][j + 1];
            int s2 = sh_s[wid][j + 2], s3 = sh_s[wid][j + 3];
            float wa = whp[j], wb = whp[j + 1], wc = whp[j + 2], wd = whp[j + 3];
            float4 h0 = *(const float4*)&g_h[(size_t)s0 * HC + lane * 4];
            float4 h1 = *(const float4*)&g_h[(size_t)s1 * HC + lane * 4];
            float4 h2 = *(const float4*)&g_h[(size_t)s2 * HC + lane * 4];
            float4 h3 = *(const float4*)&g_h[(size_t)s3 * HC + lane * 4];
            den += (wa + wb) + (wc + wd);
            acc0 += h0.x * wa + h1.x * wb + h2.x * wc + h3.x * wd;
            acc1 += h0.y * wa + h1.y * wb + h2.y * wc + h3.y * wd;
            acc2 += h0.z * wa + h1.z * wb + h2.z * wc + h3.z * wd;
            acc3 += h0.w * wa + h1.w * wb + h2.w * wc + h3.w * wd;
        }
        __syncwarp();
    }

    float inv = 1.f / (den + 1e-16f);
    float4 bv = *(const float4*)&bias[lane * 4];
    float v0 = fmaxf(acc0 * inv + bv.x, 0.f);
    float v1 = fmaxf(acc1 * inv + bv.y, 0.f);
    float v2 = fmaxf(acc2 * inv + bv.z, 0.f);
    float v3 = fmaxf(acc3 * inv + bv.w, 0.f);

    float fa[NCLS];
    int k0 = lane * 4;
    #pragma unroll
    for (int c = 0; c < NCLS; c++) {
        const float* wr = &wt[c * HC + k0];
        fa[c] = v0 * wr[0] + v1 * wr[1] + v2 * wr[2] + v3 * wr[3];
    }
    #pragma unroll
    for (int c = 0; c < NCLS; c++)
        #pragma unroll
        for (int o = 16; o; o >>= 1) fa[c] += __shfl_xor_sync(0xffffffffu, fa[c], o);

    if (lane == 0) {
        float mx = -CUDART_INF_F;
        #pragma unroll
        for (int c = 0; c < NCLS; c++) { fa[c] += bfc[c]; mx = fmaxf(mx, fa[c]); }
        float se = 0.f;
        #pragma unroll
        for (int c = 0; c < NCLS; c++) se += __expf(fa[c] - mx);
        float lse = mx + logf(se);
        #pragma unroll
        for (int c = 0; c < NCLS; c++) out[(size_t)node * NCLS + c] = fa[c] - lse;
    }
}

// ---------------- launch ----------------------------------------------------
extern "C" void kernel_launch(void* const* d_in, const int* in_sizes, int n_in,
                              void* d_out, int out_size) {
    const float* x       = (const float*)d_in[0];
    const void*  ei      = d_in[1];
    const float* W       = (const float*)d_in[2];
    const float* att_src = (const float*)d_in[3];
    const float* att_dst = (const float*)d_in[4];
    const float* bias    = (const float*)d_in[5];
    const float* Wfc     = (const float*)d_in[6];
    const float* bfc     = (const float*)d_in[7];
    float* out = (float*)d_out;

    k_init<<<(NNODES + 255) / 256, 256>>>(ei);

    dim3 gg(2, (NNODES + 63) / 64);
    k_gemm<<<gg, 256>>>(x, W, att_src, att_dst);

    k_count<<<(ETOT + 255) / 256, 256>>>(ei);
    k_scan<<<1, SCAN_T>>>();
    k_fill<<<(ETOT + 255) / 256, 256>>>(ei);

    k_agg<<<(NNODES + WPB - 1) / WPB, 256>>>(bias, Wfc, bfc, out);
}

// round 5
// speedup vs baseline: 2.4778x; 1.2681x over previous
#include <cuda_runtime.h>
#include <math_constants.h>

#define NNODES 50000
#define EEDGES 800000
#define ETOT   (EEDGES + NNODES)
#define FIN    128
#define HC     128
#define NHEAD  2
#define NCLS   16
#define NEG    0.2f
#define WPB    8

// ---------------- scratch ----------------
__device__ float g_h[(size_t)NNODES * HC];
__device__ float g_asrc[NNODES * NHEAD];
__device__ float g_adst[NNODES * NHEAD];
__device__ int   g_cnt[NNODES];          // degree (persist; used by k_agg)
__device__ int   g_cur[NNODES];          // fill cursors
__device__ int   g_off[NNODES];          // bucket base (arbitrary order)
__device__ int   g_csrc[ETOT];           // CSR src lists (dst-major)
__device__ int   g_es[ETOT];             // decoded src (int32)
__device__ int   g_ed[ETOT];             // decoded dst (int32)
__device__ int   g_total;                // bucket allocator cursor
__device__ int   g_idx64;

__device__ __forceinline__ void load_edge(const void* ei, int t, int& s, int& d) {
    if (t >= EEDGES) { s = d = t - EEDGES; return; }
    if (g_idx64) {
        const long long* p = (const long long*)ei;
        s = (int)p[t]; d = (int)p[EEDGES + t];
    } else {
        const int* p = (const int*)ei;
        s = p[t]; d = p[EEDGES + t];
    }
}

// ---------------- init: zero counters + warp-parallel dtype detect ---------
__global__ void k_init(const void* ei) {
    int i = blockIdx.x * blockDim.x + threadIdx.x;
    if (i < NNODES) { g_cnt[i] = 0; g_cur[i] = 0; }
    if (i == 0) g_total = 0;
    if (blockIdx.x == 0 && threadIdx.x < 32) {
        const long long* p = (const long long*)ei;
        int ok = 1;
        #pragma unroll
        for (int r = 0; r < 8; r++) {
            long long v = p[threadIdx.x + r * 32];
            if (v < 0 || v >= NNODES) ok = 0;
        }
        ok = __all_sync(0xffffffffu, ok);
        if (threadIdx.x == 0) g_idx64 = ok;
    }
}

// ---------------- h = x @ W with fused attention-coefficient epilogue ------
__global__ void k_gemm(const float* __restrict__ x, const float* __restrict__ W,
                       const float* __restrict__ att_src, const float* __restrict__ att_dst) {
    __shared__ float xs[64][32];
    __shared__ float ws[32][64];
    int tid = threadIdx.x;
    int head = blockIdx.x;
    int col0 = head * 64;
    int row0 = blockIdx.y * 64;
    int ty = tid >> 4, tx = tid & 15;
    float acc[4][4] = {};

    for (int kt = 0; kt < FIN; kt += 32) {
        #pragma unroll
        for (int i = 0; i < 2; i++) {
            int lin = tid + i * 256;
            int r = lin >> 3, kk = (lin & 7) << 2;
            int gr = row0 + r;
            float4 v = make_float4(0.f, 0.f, 0.f, 0.f);
            if (gr < NNODES) v = *(const float4*)&x[(size_t)gr * FIN + kt + kk];
            xs[r][kk] = v.x; xs[r][kk + 1] = v.y; xs[r][kk + 2] = v.z; xs[r][kk + 3] = v.w;
        }
        #pragma unroll
        for (int i = 0; i < 2; i++) {
            int lin = tid + i * 256;
            int k = lin >> 4, cc = (lin & 15) << 2;
            float4 v = *(const float4*)&W[(size_t)(kt + k) * HC + col0 + cc];
            ws[k][cc] = v.x; ws[k][cc + 1] = v.y; ws[k][cc + 2] = v.z; ws[k][cc + 3] = v.w;
        }
        __syncthreads();
        #pragma unroll
        for (int k = 0; k < 32; k++) {
            float a[4], b[4];
            #pragma unroll
            for (int i = 0; i < 4; i++) a[i] = xs[ty * 4 + i][k];
            #pragma unroll
            for (int j = 0; j < 4; j++) b[j] = ws[k][tx * 4 + j];
            #pragma unroll
            for (int i = 0; i < 4; i++)
                #pragma unroll
                for (int j = 0; j < 4; j++)
                    acc[i][j] += a[i] * b[j];
        }
        __syncthreads();
    }

    float asv[4], adv[4];
    #pragma unroll
    for (int j = 0; j < 4; j++) {
        asv[j] = att_src[col0 + tx * 4 + j];
        adv[j] = att_dst[col0 + tx * 4 + j];
    }

    float ps[4], pd[4];
    #pragma unroll
    for (int i = 0; i < 4; i++) {
        int gr = row0 + ty * 4 + i;
        ps[i] = acc[i][0] * asv[0] + acc[i][1] * asv[1] + acc[i][2] * asv[2] + acc[i][3] * asv[3];
        pd[i] = acc[i][0] * adv[0] + acc[i][1] * adv[1] + acc[i][2] * adv[2] + acc[i][3] * adv[3];
        if (gr < NNODES)
            *(float4*)&g_h[(size_t)gr * HC + col0 + tx * 4] =
                make_float4(acc[i][0], acc[i][1], acc[i][2], acc[i][3]);
    }
    #pragma unroll
    for (int o = 8; o; o >>= 1) {
        #pragma unroll
        for (int i = 0; i < 4; i++) {
            ps[i] += __shfl_xor_sync(0xffffffffu, ps[i], o);
            pd[i] += __shfl_xor_sync(0xffffffffu, pd[i], o);
        }
    }
    if (tx == 0) {
        #pragma unroll
        for (int i = 0; i < 4; i++) {
            int gr = row0 + ty * 4 + i;
            if (gr < NNODES) {
                g_asrc[gr * 2 + head] = ps[i];
                g_adst[gr * 2 + head] = pd[i];
            }
        }
    }
}

// ---------------- CSR build: count (+ decode), alloc, fill ------------------
__global__ void k_count(const void* __restrict__ ei) {
    int t = blockIdx.x * blockDim.x + threadIdx.x;
    if (t >= ETOT) return;
    int s, d; load_edge(ei, t, s, d);
    g_es[t] = s; g_ed[t] = d;
    atomicAdd(&g_cnt[d], 1);
}

// warp-aggregated bucket allocation: one atomicAdd per warp
__global__ void k_alloc() {
    int i = blockIdx.x * blockDim.x + threadIdx.x;
    int lane = threadIdx.x & 31;
    int cnt = (i < NNODES) ? g_cnt[i] : 0;
    int pre = cnt;
    #pragma unroll
    for (int o = 1; o < 32; o <<= 1) {
        int v = __shfl_up_sync(0xffffffffu, pre, o);
        if (lane >= o) pre += v;
    }
    int tot = __shfl_sync(0xffffffffu, pre, 31);
    int base = 0;
    if (lane == 31) base = atomicAdd(&g_total, tot);
    base = __shfl_sync(0xffffffffu, base, 31);
    if (i < NNODES) g_off[i] = base + pre - cnt;
}

__global__ void k_fill() {
    int t = blockIdx.x * blockDim.x + threadIdx.x;
    if (t >= ETOT) return;
    int s = g_es[t], d = g_ed[t];
    int pos = g_off[d] + atomicAdd(&g_cur[d], 1);
    g_csrc[pos] = s;
}

// ---------------- fused softmax-aggregate + bias/relu/fc/log_softmax --------
__global__ void k_agg(const float* __restrict__ bias, const float* __restrict__ Wfc,
                      const float* __restrict__ bfc, float* __restrict__ out) {
    __shared__ float wt[NCLS * HC];
    __shared__ int   sh_s[WPB][32];
    __shared__ float sh_w0[WPB][32];
    __shared__ float sh_w1[WPB][32];
    int tid = threadIdx.x;
    for (int i = tid; i < NCLS * HC; i += blockDim.x) {
        int c = i >> 7, k = i & 127;
        wt[i] = Wfc[k * NCLS + c];
    }
    __syncthreads();

    int wid = tid >> 5, lane = tid & 31;
    int node = blockIdx.x * WPB + wid;
    if (node >= NNODES) return;

    int off = g_off[node];
    int deg = g_cnt[node];
    float ad0 = g_adst[node * 2], ad1 = g_adst[node * 2 + 1];
    int head = lane >> 4;

    float acc0 = 0.f, acc1 = 0.f, acc2 = 0.f, acc3 = 0.f, den = 0.f;

    for (int base = 0; base < deg; base += 32) {
        int i = base + lane;
        int s = 0; float w0 = 0.f, w1 = 0.f;
        if (i < deg) {
            s = g_csrc[off + i];
            float2 as = *(const float2*)&g_asrc[s * 2];
            float e0 = as.x + ad0, e1 = as.y + ad1;
            e0 = e0 > 0.f ? e0 : NEG * e0;
            e1 = e1 > 0.f ? e1 : NEG * e1;
            w0 = __expf(e0); w1 = __expf(e1);
        }
        sh_s[wid][lane] = s; sh_w0[wid][lane] = w0; sh_w1[wid][lane] = w1;
        __syncwarp();

        int nthis = deg - base; if (nthis > 32) nthis = 32;
        int nproc = (nthis + 3) & ~3;
        const float* whp = head ? sh_w1[wid] : sh_w0[wid];
        for (int j = 0; j < nproc; j += 4) {
            int s0 = sh_s[wid][j], s1 = sh_s[wid][j + 1];
            int s2 = sh_s[wid][j + 2], s3 = sh_s[wid][j + 3];
            float wa = whp[j], wb = whp[j + 1], wc = whp[j + 2], wd = whp[j + 3];
            float4 h0 = *(const float4*)&g_h[(size_t)s0 * HC + lane * 4];
            float4 h1 = *(const float4*)&g_h[(size_t)s1 * HC + lane * 4];
            float4 h2 = *(const float4*)&g_h[(size_t)s2 * HC + lane * 4];
            float4 h3 = *(const float4*)&g_h[(size_t)s3 * HC + lane * 4];
            den += (wa + wb) + (wc + wd);
            acc0 += h0.x * wa + h1.x * wb + h2.x * wc + h3.x * wd;
            acc1 += h0.y * wa + h1.y * wb + h2.y * wc + h3.y * wd;
            acc2 += h0.z * wa + h1.z * wb + h2.z * wc + h3.z * wd;
            acc3 += h0.w * wa + h1.w * wb + h2.w * wc + h3.w * wd;
        }
        __syncwarp();
    }

    float inv = 1.f / (den + 1e-16f);
    float4 bv = *(const float4*)&bias[lane * 4];
    float v0 = fmaxf(acc0 * inv + bv.x, 0.f);
    float v1 = fmaxf(acc1 * inv + bv.y, 0.f);
    float v2 = fmaxf(acc2 * inv + bv.z, 0.f);
    float v3 = fmaxf(acc3 * inv + bv.w, 0.f);

    float fa[NCLS];
    int k0 = lane * 4;
    #pragma unroll
    for (int c = 0; c < NCLS; c++) {
        const float* wr = &wt[c * HC + k0];
        fa[c] = v0 * wr[0] + v1 * wr[1] + v2 * wr[2] + v3 * wr[3];
    }
    #pragma unroll
    for (int c = 0; c < NCLS; c++)
        #pragma unroll
        for (int o = 16; o; o >>= 1) fa[c] += __shfl_xor_sync(0xffffffffu, fa[c], o);

    if (lane == 0) {
        float mx = -CUDART_INF_F;
        #pragma unroll
        for (int c = 0; c < NCLS; c++) { fa[c] += bfc[c]; mx = fmaxf(mx, fa[c]); }
        float se = 0.f;
        #pragma unroll
        for (int c = 0; c < NCLS; c++) se += __expf(fa[c] - mx);
        float lse = mx + logf(se);
        #pragma unroll
        for (int c = 0; c < NCLS; c++) out[(size_t)node * NCLS + c] = fa[c] - lse;
    }
}

// ---------------- launch ----------------------------------------------------
extern "C" void kernel_launch(void* const* d_in, const int* in_sizes, int n_in,
                              void* d_out, int out_size) {
    const float* x       = (const float*)d_in[0];
    const void*  ei      = d_in[1];
    const float* W       = (const float*)d_in[2];
    const float* att_src = (const float*)d_in[3];
    const float* att_dst = (const float*)d_in[4];
    const float* bias    = (const float*)d_in[5];
    const float* Wfc     = (const float*)d_in[6];
    const float* bfc     = (const float*)d_in[7];
    float* out = (float*)d_out;

    k_init<<<(NNODES + 255) / 256, 256>>>(ei);

    dim3 gg(2, (NNODES + 63) / 64);
    k_gemm<<<gg, 256>>>(x, W, att_src, att_dst);

    k_count<<<(ETOT + 255) / 256, 256>>>(ei);
    k_alloc<<<(NNODES + 255) / 256, 256>>>();
    k_fill<<<(ETOT + 255) / 256, 256>>>();

    k_agg<<<(NNODES + WPB - 1) / WPB, 256>>>(bias, Wfc, bfc, out);
}

// round 6
// speedup vs baseline: 2.6734x; 1.0789x over previous
#include <cuda_runtime.h>
#include <cuda_fp16.h>
#include <math_constants.h>

#define NNODES 50000
#define EEDGES 800000
#define ETOT   (EEDGES + NNODES)
#define FIN    128
#define HC     128
#define NHEAD  2
#define NCLS   16
#define NEG    0.2f
#define WPB    8
#define GEMM_BLKS (2 * ((NNODES + 63) / 64))   // 1564
#define CNT_BLKS  ((ETOT + 255) / 256)         // 3321

// ---------------- scratch ----------------
__device__ __half g_hh[(size_t)NNODES * HC];   // 12.8 MB, gather source
__device__ float  g_asrc[NNODES * NHEAD];
__device__ float  g_adst[NNODES * NHEAD];
__device__ int    g_cnt[NNODES];
__device__ int    g_cur[NNODES];
__device__ int    g_off[NNODES];
__device__ int    g_csrc[ETOT];
__device__ int    g_es[ETOT];
__device__ int    g_ed[ETOT];
__device__ int    g_total;
__device__ int    g_idx64;

__device__ __forceinline__ void load_edge(const void* ei, int t, int& s, int& d) {
    if (t >= EEDGES) { s = d = t - EEDGES; return; }
    if (g_idx64) {
        const long long* p = (const long long*)ei;
        s = (int)p[t]; d = (int)p[EEDGES + t];
    } else {
        const int* p = (const int*)ei;
        s = p[t]; d = p[EEDGES + t];
    }
}

// ---------------- init: zero counters + warp-parallel dtype detect ---------
__global__ void k_init(const void* ei) {
    int i = blockIdx.x * blockDim.x + threadIdx.x;
    if (i < NNODES) { g_cnt[i] = 0; g_cur[i] = 0; }
    if (i == 0) g_total = 0;
    if (blockIdx.x == 0 && threadIdx.x < 32) {
        const long long* p = (const long long*)ei;
        int ok = 1;
        #pragma unroll
        for (int r = 0; r < 8; r++) {
            long long v = p[threadIdx.x + r * 32];
            if (v < 0 || v >= NNODES) ok = 0;
        }
        ok = __all_sync(0xffffffffu, ok);
        if (threadIdx.x == 0) g_idx64 = ok;
    }
}

// ---------------- fused: [h = x@W + att epilogue]  ||  [edge count/decode] --
__global__ void k_gemm_count(const float* __restrict__ x, const float* __restrict__ W,
                             const float* __restrict__ att_src, const float* __restrict__ att_dst,
                             const void* __restrict__ ei) {
    __shared__ float xs[64][32];
    __shared__ float ws[32][64];
    int tid = threadIdx.x;

    if (blockIdx.x >= GEMM_BLKS) {
        // ---- edge count + decode branch ----
        int t = (blockIdx.x - GEMM_BLKS) * 256 + tid;
        if (t < ETOT) {
            int s, d; load_edge(ei, t, s, d);
            g_es[t] = s; g_ed[t] = d;
            atomicAdd(&g_cnt[d], 1);
        }
        return;
    }

    // ---- GEMM branch ----
    int head = blockIdx.x & 1;
    int col0 = head * 64;
    int row0 = (blockIdx.x >> 1) * 64;
    int ty = tid >> 4, tx = tid & 15;
    float acc[4][4] = {};

    for (int kt = 0; kt < FIN; kt += 32) {
        #pragma unroll
        for (int i = 0; i < 2; i++) {
            int lin = tid + i * 256;
            int r = lin >> 3, kk = (lin & 7) << 2;
            int gr = row0 + r;
            float4 v = make_float4(0.f, 0.f, 0.f, 0.f);
            if (gr < NNODES) v = *(const float4*)&x[(size_t)gr * FIN + kt + kk];
            xs[r][kk] = v.x; xs[r][kk + 1] = v.y; xs[r][kk + 2] = v.z; xs[r][kk + 3] = v.w;
        }
        #pragma unroll
        for (int i = 0; i < 2; i++) {
            int lin = tid + i * 256;
            int k = lin >> 4, cc = (lin & 15) << 2;
            float4 v = *(const float4*)&W[(size_t)(kt + k) * HC + col0 + cc];
            ws[k][cc] = v.x; ws[k][cc + 1] = v.y; ws[k][cc + 2] = v.z; ws[k][cc + 3] = v.w;
        }
        __syncthreads();
        #pragma unroll
        for (int k = 0; k < 32; k++) {
            float a[4], b[4];
            #pragma unroll
            for (int i = 0; i < 4; i++) a[i] = xs[ty * 4 + i][k];
            #pragma unroll
            for (int j = 0; j < 4; j++) b[j] = ws[k][tx * 4 + j];
            #pragma unroll
            for (int i = 0; i < 4; i++)
                #pragma unroll
                for (int j = 0; j < 4; j++)
                    acc[i][j] += a[i] * b[j];
        }
        __syncthreads();
    }

    float asv[4], adv[4];
    #pragma unroll
    for (int j = 0; j < 4; j++) {
        asv[j] = att_src[col0 + tx * 4 + j];
        adv[j] = att_dst[col0 + tx * 4 + j];
    }

    float ps[4], pd[4];
    #pragma unroll
    for (int i = 0; i < 4; i++) {
        int gr = row0 + ty * 4 + i;
        ps[i] = acc[i][0] * asv[0] + acc[i][1] * asv[1] + acc[i][2] * asv[2] + acc[i][3] * asv[3];
        pd[i] = acc[i][0] * adv[0] + acc[i][1] * adv[1] + acc[i][2] * adv[2] + acc[i][3] * adv[3];
        if (gr < NNODES) {
            __half2 p0 = __float22half2_rn(make_float2(acc[i][0], acc[i][1]));
            __half2 p1 = __float22half2_rn(make_float2(acc[i][2], acc[i][3]));
            uint2 pk = make_uint2(*(unsigned*)&p0, *(unsigned*)&p1);
            *(uint2*)&g_hh[(size_t)gr * HC + col0 + tx * 4] = pk;
        }
    }
    #pragma unroll
    for (int o = 8; o; o >>= 1) {
        #pragma unroll
        for (int i = 0; i < 4; i++) {
            ps[i] += __shfl_xor_sync(0xffffffffu, ps[i], o);
            pd[i] += __shfl_xor_sync(0xffffffffu, pd[i], o);
        }
    }
    if (tx == 0) {
        #pragma unroll
        for (int i = 0; i < 4; i++) {
            int gr = row0 + ty * 4 + i;
            if (gr < NNODES) {
                g_asrc[gr * 2 + head] = ps[i];
                g_adst[gr * 2 + head] = pd[i];
            }
        }
    }
}

// ---------------- warp-aggregated bucket allocation -------------------------
__global__ void k_alloc() {
    int i = blockIdx.x * blockDim.x + threadIdx.x;
    int lane = threadIdx.x & 31;
    int cnt = (i < NNODES) ? g_cnt[i] : 0;
    int pre = cnt;
    #pragma unroll
    for (int o = 1; o < 32; o <<= 1) {
        int v = __shfl_up_sync(0xffffffffu, pre, o);
        if (lane >= o) pre += v;
    }
    int tot = __shfl_sync(0xffffffffu, pre, 31);
    int base = 0;
    if (lane == 31) base = atomicAdd(&g_total, tot);
    base = __shfl_sync(0xffffffffu, base, 31);
    if (i < NNODES) g_off[i] = base + pre - cnt;
}

__global__ void k_fill() {
    int t = blockIdx.x * blockDim.x + threadIdx.x;
    if (t >= ETOT) return;
    int s = g_es[t], d = g_ed[t];
    int pos = g_off[d] + atomicAdd(&g_cur[d], 1);
    g_csrc[pos] = s;
}

// ---------------- fused softmax-aggregate + bias/relu/fc/log_softmax --------
__global__ void k_agg(const float* __restrict__ bias, const float* __restrict__ Wfc,
                      const float* __restrict__ bfc, float* __restrict__ out) {
    __shared__ float wt[NCLS * HC];
    __shared__ int   sh_s[WPB][32];
    __shared__ float sh_w0[WPB][32];
    __shared__ float sh_w1[WPB][32];
    int tid = threadIdx.x;
    for (int i = tid; i < NCLS * HC; i += blockDim.x) {
        int c = i >> 7, k = i & 127;
        wt[i] = Wfc[k * NCLS + c];
    }
    __syncthreads();

    int wid = tid >> 5, lane = tid & 31;
    int node = blockIdx.x * WPB + wid;
    if (node >= NNODES) return;

    int off = g_off[node];
    int deg = g_cnt[node];
    float ad0 = g_adst[node * 2], ad1 = g_adst[node * 2 + 1];
    int head = lane >> 4;

    float acc0 = 0.f, acc1 = 0.f, acc2 = 0.f, acc3 = 0.f, den = 0.f;

    for (int base = 0; base < deg; base += 32) {
        int i = base + lane;
        int s = 0; float w0 = 0.f, w1 = 0.f;
        if (i < deg) {
            s = g_csrc[off + i];
            float2 as = *(const float2*)&g_asrc[s * 2];
            float e0 = as.x + ad0, e1 = as.y + ad1;
            e0 = e0 > 0.f ? e0 : NEG * e0;
            e1 = e1 > 0.f ? e1 : NEG * e1;
            w0 = __expf(e0); w1 = __expf(e1);
        }
        sh_s[wid][lane] = s; sh_w0[wid][lane] = w0; sh_w1[wid][lane] = w1;
        __syncwarp();

        int nthis = deg - base; if (nthis > 32) nthis = 32;
        int nproc = (nthis + 3) & ~3;
        const float* whp = head ? sh_w1[wid] : sh_w0[wid];
        for (int j = 0; j < nproc; j += 4) {
            int s0 = sh_s[wid][j], s1 = sh_s[wid][j + 1];
            int s2 = sh_s[wid][j + 2], s3 = sh_s[wid][j + 3];
            float wa = whp[j], wb = whp[j + 1], wc = whp[j + 2], wd = whp[j + 3];
            uint2 r0 = *(const uint2*)&g_hh[(size_t)s0 * HC + lane * 4];
            uint2 r1 = *(const uint2*)&g_hh[(size_t)s1 * HC + lane * 4];
            uint2 r2 = *(const uint2*)&g_hh[(size_t)s2 * HC + lane * 4];
            uint2 r3 = *(const uint2*)&g_hh[(size_t)s3 * HC + lane * 4];
            den += (wa + wb) + (wc + wd);
            float2 a01 = __half22float2(*(__half2*)&r0.x), a23 = __half22float2(*(__half2*)&r0.y);
            float2 b01 = __half22float2(*(__half2*)&r1.x), b23 = __half22float2(*(__half2*)&r1.y);
            float2 c01 = __half22float2(*(__half2*)&r2.x), c23 = __half22float2(*(__half2*)&r2.y);
            float2 d01 = __half22float2(*(__half2*)&r3.x), d23 = __half22float2(*(__half2*)&r3.y);
            acc0 += a01.x * wa + b01.x * wb + c01.x * wc + d01.x * wd;
            acc1 += a01.y * wa + b01.y * wb + c01.y * wc + d01.y * wd;
            acc2 += a23.x * wa + b23.x * wb + c23.x * wc + d23.x * wd;
            acc3 += a23.y * wa + b23.y * wb + c23.y * wc + d23.y * wd;
        }
        __syncwarp();
    }

    float inv = 1.f / (den + 1e-16f);
    float4 bv = *(const float4*)&bias[lane * 4];
    float v0 = fmaxf(acc0 * inv + bv.x, 0.f);
    float v1 = fmaxf(acc1 * inv + bv.y, 0.f);
    float v2 = fmaxf(acc2 * inv + bv.z, 0.f);
    float v3 = fmaxf(acc3 * inv + bv.w, 0.f);

    float fa[NCLS];
    int k0 = lane * 4;
    #pragma unroll
    for (int c = 0; c < NCLS; c++) {
        const float* wr = &wt[c * HC + k0];
        fa[c] = v0 * wr[0] + v1 * wr[1] + v2 * wr[2] + v3 * wr[3];
    }
    #pragma unroll
    for (int c = 0; c < NCLS; c++)
        #pragma unroll
        for (int o = 16; o; o >>= 1) fa[c] += __shfl_xor_sync(0xffffffffu, fa[c], o);

    if (lane == 0) {
        float mx = -CUDART_INF_F;
        #pragma unroll
        for (int c = 0; c < NCLS; c++) { fa[c] += bfc[c]; mx = fmaxf(mx, fa[c]); }
        float se = 0.f;
        #pragma unroll
        for (int c = 0; c < NCLS; c++) se += __expf(fa[c] - mx);
        float lse = mx + logf(se);
        #pragma unroll
        for (int c = 0; c < NCLS; c++) out[(size_t)node * NCLS + c] = fa[c] - lse;
    }
}

// ---------------- launch ----------------------------------------------------
extern "C" void kernel_launch(void* const* d_in, const int* in_sizes, int n_in,
                              void* d_out, int out_size) {
    const float* x       = (const float*)d_in[0];
    const void*  ei      = d_in[1];
    const float* W       = (const float*)d_in[2];
    const float* att_src = (const float*)d_in[3];
    const float* att_dst = (const float*)d_in[4];
    const float* bias    = (const float*)d_in[5];
    const float* Wfc     = (const float*)d_in[6];
    const float* bfc     = (const float*)d_in[7];
    float* out = (float*)d_out;

    k_init<<<(NNODES + 255) / 256, 256>>>(ei);
    k_gemm_count<<<GEMM_BLKS + CNT_BLKS, 256>>>(x, W, att_src, att_dst, ei);
    k_alloc<<<(NNODES + 255) / 256, 256>>>();
    k_fill<<<(ETOT + 255) / 256, 256>>>();
    k_agg<<<(NNODES + WPB - 1) / WPB, 256>>>(bias, Wfc, bfc, out);
}